// round 17
// baseline (speedup 1.0000x reference)
#include <cuda_runtime.h>

// Problem constants (static per init_kwargs)
#define N_IMG 8
#define CIN   64
#define H     112
#define W     112
#define HW    12544          // H*W, patches per image (stride 1, pad 1)
#define DPAT  576            // Cin * K * K
#define COUT  64
#define MEM   1025           // memo table size

// Tiling for the fused csum+bins kernel: 16 wide x 8 tall tiles
#define TLX   16
#define TLY   8
#define HLX   18             // TLX + 2
#define HLY   10             // TLY + 2
#define NHALO (HLX * HLY)    // 180
#define TPX   7              // 112/16
#define TPY   14             // 112/8
#define FUSED_THREADS 192    // >= NHALO, multiple of 32

// Scratch (device globals — no allocation allowed).
// g_first holds ENCODED first-patch: enc = HW - p (so 0 == "empty bin").
// Zero-initialized at module load; k_scatter re-zeros it each replay, so the
// graph is self-restoring with no dedicated init kernel.
__device__ int   g_bins[N_IMG * HW];
__device__ int   g_first[N_IMG * MEM];
__device__ float g_rep[N_IMG * MEM * COUT];

// ---------------------------------------------------------------------------
// Compensated-sum helpers (all __fadd_rn: fast-math-proof).
// Kahan chain: 4 FADDs per element, serial depth 4. Invariant: true ~= s - c.
// ---------------------------------------------------------------------------
__device__ __forceinline__ void kah(float& s, float& c, float x) {
    float y = __fadd_rn(x, -c);
    float t = __fadd_rn(s, y);
    c = __fadd_rn(__fadd_rn(t, -s), -y);
    s = t;
}

// TwoSum (exact): s + e == a + b
__device__ __forceinline__ void two_sum(float a, float b, float& s, float& e) {
    s = __fadd_rn(a, b);
    float bb   = __fadd_rn(s, -a);
    float err1 = __fadd_rn(a, -__fadd_rn(s, -bb));
    float err2 = __fadd_rn(b, -bb);
    e = __fadd_rn(err1, err2);
}

// (rh, rl) = (ah, al) + (bh, bl), renormalized double-single add
__device__ __forceinline__ void df_add(float ah, float al, float bh, float bl,
                                       float& rh, float& rl) {
    float s, e;
    two_sum(ah, bh, s, e);
    e  = __fadd_rn(e, __fadd_rn(al, bl));
    rh = __fadd_rn(s, e);
    rl = __fadd_rn(e, __fadd_rn(s, -rh));
}

// ---------------------------------------------------------------------------
// Kernel 1 (fused): per-pixel 64-channel Kahan sum (4 chains, 16-wide load
// batches for MLP) into an 18x10 SMEM halo tile (one halo pixel per thread),
// then df64 3x3 box sum -> quantized summary -> bin. Compensated sum is exact
// to ~1e-11 relative — 4 orders tighter than the reference's own fp32 sum
// noise — so bins match the reference except with vanishing probability.
// Final fp32 quantize ops replicate the reference bit-exactly:
//   mean = f32(sum) / 576.0f ; q = mean * 100.0f ; summ = trunc_to_int(q)
// ---------------------------------------------------------------------------
__global__ void __launch_bounds__(FUSED_THREADS) k_fused(const float* __restrict__ fmap) {
    __shared__ float sh_hi[NHALO];
    __shared__ float sh_lo[NHALO];

    int blk = blockIdx.x;
    int n   = blk / (TPX * TPY);
    int t   = blk - n * (TPX * TPY);
    int ty  = t / TPX, tx = t - (t / TPX) * TPX;
    int gy0 = ty * TLY - 1;      // halo origin (can be -1)
    int gx0 = tx * TLX - 1;

    const float* fb = fmap + n * CIN * HW;
    int tid = threadIdx.x;

    // Phase 1: Kahan channel sums, exactly one halo pixel per thread.
    if (tid < NHALO) {
        int hy = tid / HLX;
        int hx = tid - hy * HLX;
        int gy = gy0 + hy;
        int gx = gx0 + hx;
        float s0 = 0.f, c0 = 0.f, s1 = 0.f, c1 = 0.f;
        float s2 = 0.f, c2 = 0.f, s3 = 0.f, c3 = 0.f;
        if ((unsigned)gy < H && (unsigned)gx < W) {
            const float* p = fb + gy * W + gx;
#pragma unroll
            for (int cg = 0; cg < 4; ++cg) {        // 4 groups of 16 channels
                float v[16];
#pragma unroll
                for (int i = 0; i < 16; ++i)
                    v[i] = __ldg(p + (cg * 16 + i) * HW);   // 16 loads in flight
#pragma unroll
                for (int i = 0; i < 16; i += 4) {
                    kah(s0, c0, v[i + 0]);
                    kah(s1, c1, v[i + 1]);
                    kah(s2, c2, v[i + 2]);
                    kah(s3, c3, v[i + 3]);
                }
            }
        }
        // merge the 4 chains: chain value == (s, -c) as a hi/lo pair
        float ah, al, bh, bl, rh, rl;
        df_add(s0, -c0, s1, -c1, ah, al);
        df_add(s2, -c2, s3, -c3, bh, bl);
        df_add(ah, al, bh, bl, rh, rl);
        sh_hi[tid] = rh;
        sh_lo[tid] = rl;
    }
    __syncthreads();

    // Phase 2: df64 3x3 box sum, quantize, bin, scatter first-occurrence.
    if (tid < TLX * TLY) {
        int ly = tid / TLX;
        int lx = tid - ly * TLX;
        int gy = ty * TLY + ly;
        int gx = tx * TLX + lx;

        float shi = 0.f, slo = 0.f;
#pragma unroll
        for (int dy = 0; dy < 3; ++dy)
#pragma unroll
            for (int dx = 0; dx < 3; ++dx) {
                int idx = (ly + dy) * HLX + (lx + dx);
                float rh, rl;
                df_add(shi, slo, sh_hi[idx], sh_lo[idx], rh, rl);
                shi = rh; slo = rl;
            }

        float q  = __fmul_rn(__fdiv_rn(shi, 576.0f), 100.0f);
        int summ = __float2int_rz(q);            // trunc toward zero == astype(int32)
        int bin  = summ + 512;                   // summ - MIN_SUMMARY
        bin = bin < 0 ? 0 : (bin > MEM - 1 ? MEM - 1 : bin);

        int p = gy * W + gx;
        g_bins[n * HW + p] = bin;
        atomicMax(&g_first[n * MEM + bin], HW - p);   // min-p == max-(HW-p)
    }
}

// ---------------------------------------------------------------------------
// Kernel 2: representative GEMM rows. One 64-thread block per (image, bin).
// Inactive bins (enc==0) exit immediately (~400 of 8200 blocks do work).
// Thread t stages its channel's 3x3 window into SMEM (d = c*9 + kh*3 + kw,
// matching conv_general_dilated_patches order), then computes cout t.
// ---------------------------------------------------------------------------
__global__ void k_rep(const float* __restrict__ fmap,
                      const float* __restrict__ weight,
                      const float* __restrict__ bias) {
    int n = blockIdx.x / MEM;
    int b = blockIdx.x - n * MEM;
    int enc = g_first[n * MEM + b];
    if (enc <= 0) return;                    // empty bin
    int fp = HW - enc;                       // first patch index

    __shared__ float sp[DPAT];
    int t = threadIdx.x;                     // 0..63
    int y = fp / W;
    int x = fp - y * W;

    const float* fb = fmap + (n * CIN + t) * HW;
#pragma unroll
    for (int kh = 0; kh < 3; ++kh) {
        int yy = y + kh - 1;
#pragma unroll
        for (int kw = 0; kw < 3; ++kw) {
            int xx = x + kw - 1;
            float v = 0.0f;
            if (yy >= 0 && yy < H && xx >= 0 && xx < W) v = fb[yy * W + xx];
            sp[t * 9 + kh * 3 + kw] = v;
        }
    }
    __syncthreads();

    const float4* w4 = (const float4*)(weight + t * DPAT);
    const float4* s4 = (const float4*)sp;
    float acc = __ldg(&bias[t]);
#pragma unroll 8
    for (int d = 0; d < DPAT / 4; ++d) {
        float4 wv = __ldg(&w4[d]);
        float4 sv = s4[d];
        acc = fmaf(sv.x, wv.x, acc);
        acc = fmaf(sv.y, wv.y, acc);
        acc = fmaf(sv.z, wv.z, acc);
        acc = fmaf(sv.w, wv.w, acc);
    }
    g_rep[(n * MEM + b) * COUT + t] = acc;
}

// ---------------------------------------------------------------------------
// Kernel 3: broadcast representative rows to NCHW output.
// Thread = (4 consecutive pixels, 16-cout quarter): int4 bin read, uniform-bin
// fast path (bins are spatially correlated), 16 x STG.128 where each
// warp-store covers 512B contiguous. Output is L2-absorbed (25.7MB < 126MB),
// so the ceiling is LTS issue/latency — 16 independent 128-bit stores per
// thread keep the queues full. Also re-zeros g_first for the next replay.
// ---------------------------------------------------------------------------
__global__ void k_scatter(float* __restrict__ out) {
    int tid  = threadIdx.x;
    int gidx = blockIdx.x * blockDim.x + tid;     // 0 .. 100351
    if (gidx < N_IMG * MEM) g_first[gidx] = 0;    // self-restore for replay

    int quarter = gidx / (N_IMG * HW / 4);        // 0..3
    int grp     = gidx - quarter * (N_IMG * HW / 4);
    int pix0    = grp * 4;                        // aligned, never crosses image
    int n  = pix0 / HW;
    int p0 = pix0 - n * HW;

    int4 b4 = *(const int4*)(g_bins + pix0);
    const float* repb = g_rep + n * MEM * COUT + quarter * 16;
    float* ob = out + (n * COUT + quarter * 16) * HW + p0;

    if (b4.x == b4.y && b4.x == b4.z && b4.x == b4.w) {
        // uniform-bin fast path: splat 16 channel values
        const float4* r4 = (const float4*)(repb + b4.x * COUT);
#pragma unroll
        for (int i = 0; i < 4; ++i) {
            float4 v = __ldg(&r4[i]);
            *(float4*)(ob + (4 * i + 0) * HW) = make_float4(v.x, v.x, v.x, v.x);
            *(float4*)(ob + (4 * i + 1) * HW) = make_float4(v.y, v.y, v.y, v.y);
            *(float4*)(ob + (4 * i + 2) * HW) = make_float4(v.z, v.z, v.z, v.z);
            *(float4*)(ob + (4 * i + 3) * HW) = make_float4(v.w, v.w, v.w, v.w);
        }
    } else {
        const float* r0 = repb + b4.x * COUT;
        const float* r1 = repb + b4.y * COUT;
        const float* r2 = repb + b4.z * COUT;
        const float* r3 = repb + b4.w * COUT;
#pragma unroll
        for (int c = 0; c < 16; ++c) {
            float4 o = make_float4(__ldg(r0 + c), __ldg(r1 + c),
                                   __ldg(r2 + c), __ldg(r3 + c));
            *(float4*)(ob + c * HW) = o;
        }
    }
}

// ---------------------------------------------------------------------------
extern "C" void kernel_launch(void* const* d_in, const int* in_sizes, int n_in,
                              void* d_out, int out_size) {
    const float* fmap   = (const float*)d_in[0];   // [8,64,112,112]
    const float* weight = (const float*)d_in[1];   // [64,576]
    const float* bias   = (const float*)d_in[2];   // [64]
    float* out = (float*)d_out;                    // [8,64,112,112]
    (void)in_sizes; (void)n_in; (void)out_size;

    k_fused<<<N_IMG * TPX * TPY, FUSED_THREADS>>>(fmap);   // 784 blocks
    k_rep<<<N_IMG * MEM, COUT>>>(fmap, weight, bias);      // 8200 blocks (~400 active)
    k_scatter<<<N_IMG * HW / 4 / 64, 256>>>(out);          // 392 blocks, 100352 thr
}